// round 1
// baseline (speedup 1.0000x reference)
#include <cuda_runtime.h>
#include <math.h>

#define HH   1024
#define NH   32
#define LLEN 4096
#define BA   64   // inner l (a)
#define BB   64   // outer l blocks (b), l = b*64 + a

__global__ __launch_bounds__(256) void s4d_kernel(
    const float* __restrict__ log_dt,
    const float* __restrict__ C_real,
    const float* __restrict__ log_A_real,
    const float* __restrict__ A_imag,
    float* __restrict__ out)
{
    __shared__ __align__(16) float Pr[NH][BA];
    __shared__ __align__(16) float Pi[NH][BA];
    __shared__ __align__(16) float Qr[NH][BB];
    __shared__ __align__(16) float Qi[NH][BB];
    __shared__ double sdtAr[NH], sdtAi[NH], sCdr[NH], sCdi[NH];

    const int h   = blockIdx.x;
    const int tid = threadIdx.x;

    const float dt = expf(log_dt[h]);

    // ---- per-(h,n) scalars: dtA and discretized C (double, once per n) ----
    if (tid < NH) {
        const int n = tid;
        const float Arf = -expf(log_A_real[h * NH + n]);
        const float Aif = A_imag[h * NH + n];
        const float dtArf = dt * Arf;   // match reference f32 product
        const float dtAif = dt * Aif;
        const double er = exp((double)dtArf);
        double sy, cy;
        sincos((double)dtAif, &sy, &cy);
        const double numr = er * cy - 1.0;
        const double numi = er * sy;
        const double den  = (double)Arf * (double)Arf + (double)Aif * (double)Aif;
        const double tr = (numr * (double)Arf + numi * (double)Aif) / den;
        const double ti = (numi * (double)Arf - numr * (double)Aif) / den;
        const float Cr = C_real[(h * NH + n) * 2 + 0];
        const float Ci = C_real[(h * NH + n) * 2 + 1];
        sCdr[n] = 2.0 * ((double)Cr * tr - (double)Ci * ti);   // fold the 2x here
        sCdi[n] = 2.0 * ((double)Cr * ti + (double)Ci * tr);
        sdtAr[n] = (double)dtArf;
        sdtAi[n] = (double)dtAif;
    }
    __syncthreads();

    // ---- anchors: P[n][a] = 2*Cd*exp(dtA*a), Q[n][b] = exp(dtA*64b) ----
    const double INV2PI = 0.15915494309189534561;
    const double TWOPI  = 6.28318530717958647693;
    for (int e = tid; e < NH * 128; e += 256) {
        const int n   = e >> 7;
        const int idx = e & 127;
        const double lv = (idx < BA) ? (double)idx : (double)((idx - BA) * BA);
        const double mr = sdtAr[n] * lv;
        const double ph = sdtAi[n] * lv;
        const double kk = rint(ph * INV2PI);
        const float red = (float)fma(-kk, TWOPI, ph);   // |red| <= pi, exact to ~1e-12
        float sf, cf;
        __sincosf(red, &sf, &cf);
        const float ef = __expf((float)mr);
        const float wr = ef * cf;
        const float wi = ef * sf;
        if (idx < BA) {
            const float cdr = (float)sCdr[n], cdi = (float)sCdi[n];
            Pr[n][idx] = cdr * wr - cdi * wi;
            Pi[n][idx] = cdr * wi + cdi * wr;
        } else {
            Qr[n][idx - BA] = wr;
            Qi[n][idx - BA] = wi;
        }
    }
    __syncthreads();

    // ---- 64x64x32 real GEMM: K[b*64+a] = sum_n Pr*Qr - Pi*Qi ----
    const int tx = tid & 15;   // a tile (fast output dim -> coalesced stores)
    const int ty = tid >> 4;   // b tile
    const int a0 = tx * 4;
    const int b0 = ty * 4;

    float acc[4][4];
    #pragma unroll
    for (int j = 0; j < 4; j++)
        #pragma unroll
        for (int i = 0; i < 4; i++) acc[j][i] = 0.0f;

    #pragma unroll 8
    for (int n = 0; n < NH; n++) {
        const float4 pr = *(const float4*)&Pr[n][a0];
        const float4 pi = *(const float4*)&Pi[n][a0];
        const float4 qr = *(const float4*)&Qr[n][b0];
        const float4 qi = *(const float4*)&Qi[n][b0];
        const float prv[4] = {pr.x, pr.y, pr.z, pr.w};
        const float piv[4] = {pi.x, pi.y, pi.z, pi.w};
        const float qrv[4] = {qr.x, qr.y, qr.z, qr.w};
        const float qiv[4] = {qi.x, qi.y, qi.z, qi.w};
        #pragma unroll
        for (int j = 0; j < 4; j++) {
            #pragma unroll
            for (int i = 0; i < 4; i++) {
                acc[j][i] = fmaf(prv[i],  qrv[j], acc[j][i]);
                acc[j][i] = fmaf(-piv[i], qiv[j], acc[j][i]);  // neg folds into FFMA
            }
        }
    }

    float* outh = out + (size_t)h * LLEN;
    #pragma unroll
    for (int j = 0; j < 4; j++) {
        const float4 v = make_float4(acc[j][0], acc[j][1], acc[j][2], acc[j][3]);
        *(float4*)&outh[(b0 + j) * BA + a0] = v;
    }
}

extern "C" void kernel_launch(void* const* d_in, const int* in_sizes, int n_in,
                              void* d_out, int out_size)
{
    const float* log_dt     = (const float*)d_in[0];
    const float* C_real     = (const float*)d_in[1];
    const float* log_A_real = (const float*)d_in[2];
    const float* A_imag     = (const float*)d_in[3];
    float* out = (float*)d_out;
    s4d_kernel<<<HH, 256>>>(log_dt, C_real, log_A_real, A_imag, out);
}